// round 1
// baseline (speedup 1.0000x reference)
#include <cuda_runtime.h>

#define SQ 4096
#define DM 1024
#define NH 16
#define HS 64
#define QSCALE 0.125f   // 1/sqrt(64)

// -------- scratch (no allocations allowed) --------
__device__ float g_q[NH * SQ * HS];
__device__ float g_k[NH * SQ * HS];
__device__ float g_v[NH * SQ * HS];
__device__ float g_attn[SQ * DM];

// ============================================================================
// GEMM: out = A[M,K] @ W[N,K]^T + bias   (M=4096, N=K=1024)
// 128x128 block, BK=8, 256 threads, 8x8 per thread as 2x2 blocks of 4x4.
// HEAD_LAYOUT: scatter output column j into head layout [j/64][row][j%64].
// ============================================================================
template <bool HEAD_LAYOUT>
__global__ __launch_bounds__(256)
void gemm_bias_kernel(const float* __restrict__ A,
                      const float* __restrict__ W,
                      const float* __restrict__ bias,
                      float* __restrict__ out)
{
    __shared__ float As[8][132];
    __shared__ float Bs[8][132];

    const int tid = threadIdx.x;
    const int ty  = tid >> 4;     // 0..15
    const int tx  = tid & 15;     // 0..15
    const int blockM = blockIdx.y * 128;
    const int blockN = blockIdx.x * 128;

    const int lr = tid >> 1;          // load row 0..127
    const int lk = (tid & 1) * 4;     // load k offset 0 or 4

    float acc[2][2][4][4];
#pragma unroll
    for (int a = 0; a < 2; a++)
#pragma unroll
        for (int b = 0; b < 2; b++)
#pragma unroll
            for (int i = 0; i < 4; i++)
#pragma unroll
                for (int j = 0; j < 4; j++) acc[a][b][i][j] = 0.f;

    const float* Aptr = A + (size_t)(blockM + lr) * DM + lk;
    const float* Wptr = W + (size_t)(blockN + lr) * DM + lk;

    for (int k0 = 0; k0 < DM; k0 += 8) {
        float4 av = *(const float4*)(Aptr + k0);
        float4 wv = *(const float4*)(Wptr + k0);
        __syncthreads();
        As[lk + 0][lr] = av.x; As[lk + 1][lr] = av.y;
        As[lk + 2][lr] = av.z; As[lk + 3][lr] = av.w;
        Bs[lk + 0][lr] = wv.x; Bs[lk + 1][lr] = wv.y;
        Bs[lk + 2][lr] = wv.z; Bs[lk + 3][lr] = wv.w;
        __syncthreads();

#pragma unroll
        for (int kk = 0; kk < 8; kk++) {
            float4 a0 = *(const float4*)&As[kk][ty * 4];
            float4 a1 = *(const float4*)&As[kk][64 + ty * 4];
            float4 b0 = *(const float4*)&Bs[kk][tx * 4];
            float4 b1 = *(const float4*)&Bs[kk][64 + tx * 4];
            float af[2][4] = {{a0.x, a0.y, a0.z, a0.w}, {a1.x, a1.y, a1.z, a1.w}};
            float bf[2][4] = {{b0.x, b0.y, b0.z, b0.w}, {b1.x, b1.y, b1.z, b1.w}};
#pragma unroll
            for (int ra = 0; ra < 2; ra++)
#pragma unroll
                for (int cb = 0; cb < 2; cb++)
#pragma unroll
                    for (int i = 0; i < 4; i++)
#pragma unroll
                        for (int j = 0; j < 4; j++)
                            acc[ra][cb][i][j] += af[ra][i] * bf[cb][j];
        }
    }

    // epilogue: bias + store
#pragma unroll
    for (int ra = 0; ra < 2; ra++) {
#pragma unroll
        for (int cb = 0; cb < 2; cb++) {
            const int col0 = blockN + cb * 64 + tx * 4;
            float4 bv = *(const float4*)(bias + col0);
#pragma unroll
            for (int i = 0; i < 4; i++) {
                const int row = blockM + ra * 64 + ty * 4 + i;
                float4 r;
                r.x = acc[ra][cb][i][0] + bv.x;
                r.y = acc[ra][cb][i][1] + bv.y;
                r.z = acc[ra][cb][i][2] + bv.z;
                r.w = acc[ra][cb][i][3] + bv.w;
                if (HEAD_LAYOUT) {
                    const int h = col0 >> 6;       // whole float4 within one head
                    const int d = col0 & 63;
                    *(float4*)(out + (size_t)h * SQ * HS + (size_t)row * HS + d) = r;
                } else {
                    *(float4*)(out + (size_t)row * DM + col0) = r;
                }
            }
        }
    }
}

// ============================================================================
// Flash attention (fp32, causal). Q,K,V: [H][S][64]. Out: [S][D] head-packed.
// Block = 64 queries x one head. 256 threads, each owns 4 q-rows x 4 cols.
// ============================================================================
__global__ __launch_bounds__(256)
void attn_kernel(const float* __restrict__ Q,
                 const float* __restrict__ K,
                 const float* __restrict__ V,
                 float* __restrict__ Out)
{
    extern __shared__ float sm[];
    float* Qs = sm;               // [d][q] stride 68 (transposed, pre-scaled)
    float* Ks = sm + 4352;        // [d][k] stride 68 (transposed)
    float* Vs = sm + 2 * 4352;    // [k][d] stride 68 (natural)
    float* Ps = sm + 3 * 4352;    // [k][q] stride 68

    const int h  = blockIdx.y;
    const int qb = gridDim.x - 1 - blockIdx.x;   // heavy blocks first
    const int tid = threadIdx.x;
    const int ty = tid >> 4;
    const int tx = tid & 15;

    const float* Qh = Q + (size_t)h * SQ * HS;
    const float* Kh = K + (size_t)h * SQ * HS;
    const float* Vh = V + (size_t)h * SQ * HS;

    // load Q tile transposed + scaled (once)
#pragma unroll
    for (int it = 0; it < 4; it++) {
        const int idx = tid + it * 256;
        const int r  = idx >> 4;
        const int c4 = (idx & 15) * 4;
        float4 qv = *(const float4*)(Qh + (size_t)(qb * 64 + r) * HS + c4);
        Qs[(c4 + 0) * 68 + r] = qv.x * QSCALE;
        Qs[(c4 + 1) * 68 + r] = qv.y * QSCALE;
        Qs[(c4 + 2) * 68 + r] = qv.z * QSCALE;
        Qs[(c4 + 3) * 68 + r] = qv.w * QSCALE;
    }

    float m_[4], l_[4], o_[4][4];
#pragma unroll
    for (int i = 0; i < 4; i++) {
        m_[i] = -1e30f; l_[i] = 0.f;
#pragma unroll
        for (int j = 0; j < 4; j++) o_[i][j] = 0.f;
    }
    __syncthreads();

    for (int kt = 0; kt <= qb; kt++) {
        // load K (transposed) and V (natural) tiles
#pragma unroll
        for (int it = 0; it < 4; it++) {
            const int idx = tid + it * 256;
            const int r  = idx >> 4;
            const int c4 = (idx & 15) * 4;
            float4 kv = *(const float4*)(Kh + (size_t)(kt * 64 + r) * HS + c4);
            Ks[(c4 + 0) * 68 + r] = kv.x;
            Ks[(c4 + 1) * 68 + r] = kv.y;
            Ks[(c4 + 2) * 68 + r] = kv.z;
            Ks[(c4 + 3) * 68 + r] = kv.w;
            float4 vv = *(const float4*)(Vh + (size_t)(kt * 64 + r) * HS + c4);
            *(float4*)&Vs[r * 68 + c4] = vv;
        }
        __syncthreads();

        // S = Q K^T
        float s[4][4];
#pragma unroll
        for (int i = 0; i < 4; i++)
#pragma unroll
            for (int j = 0; j < 4; j++) s[i][j] = 0.f;

#pragma unroll 8
        for (int d = 0; d < 64; d++) {
            float4 qv = *(const float4*)&Qs[d * 68 + ty * 4];
            float4 kv = *(const float4*)&Ks[d * 68 + tx * 4];
            float qf[4] = {qv.x, qv.y, qv.z, qv.w};
            float kf[4] = {kv.x, kv.y, kv.z, kv.w};
#pragma unroll
            for (int i = 0; i < 4; i++)
#pragma unroll
                for (int j = 0; j < 4; j++)
                    s[i][j] += qf[i] * kf[j];
        }

        // causal mask on the diagonal tile
        if (kt == qb) {
#pragma unroll
            for (int i = 0; i < 4; i++)
#pragma unroll
                for (int j = 0; j < 4; j++)
                    if (tx * 4 + j > ty * 4 + i) s[i][j] = -1e9f;
        }

        // online softmax (row reductions across the 16 tx-lanes)
#pragma unroll
        for (int i = 0; i < 4; i++) {
            float rm = fmaxf(fmaxf(s[i][0], s[i][1]), fmaxf(s[i][2], s[i][3]));
#pragma unroll
            for (int off = 1; off < 16; off <<= 1)
                rm = fmaxf(rm, __shfl_xor_sync(0xffffffffu, rm, off));
            const float mn = fmaxf(m_[i], rm);
            const float corr = __expf(m_[i] - mn);
            float rs = 0.f;
#pragma unroll
            for (int j = 0; j < 4; j++) {
                const float p = __expf(s[i][j] - mn);
                Ps[(tx * 4 + j) * 68 + ty * 4 + i] = p;
                rs += p;
            }
#pragma unroll
            for (int off = 1; off < 16; off <<= 1)
                rs += __shfl_xor_sync(0xffffffffu, rs, off);
            l_[i] = l_[i] * corr + rs;
            m_[i] = mn;
#pragma unroll
            for (int j = 0; j < 4; j++) o_[i][j] *= corr;
        }
        __syncthreads();

        // O += P V
#pragma unroll 8
        for (int k = 0; k < 64; k++) {
            float4 pv = *(const float4*)&Ps[k * 68 + ty * 4];
            float4 vv = *(const float4*)&Vs[k * 68 + tx * 4];
            float pf[4] = {pv.x, pv.y, pv.z, pv.w};
            float vf[4] = {vv.x, vv.y, vv.z, vv.w};
#pragma unroll
            for (int i = 0; i < 4; i++)
#pragma unroll
                for (int j = 0; j < 4; j++)
                    o_[i][j] += pf[i] * vf[j];
        }
        __syncthreads();
    }

    // normalize + write (head-packed [S][D])
#pragma unroll
    for (int i = 0; i < 4; i++) {
        const float inv = 1.f / l_[i];
        const int row = qb * 64 + ty * 4 + i;
        float4 r;
        r.x = o_[i][0] * inv; r.y = o_[i][1] * inv;
        r.z = o_[i][2] * inv; r.w = o_[i][3] * inv;
        *(float4*)(Out + (size_t)row * DM + h * HS + tx * 4) = r;
    }
}

// ============================================================================
// launch
// ============================================================================
extern "C" void kernel_launch(void* const* d_in, const int* in_sizes, int n_in,
                              void* d_out, int out_size)
{
    (void)in_sizes; (void)n_in; (void)out_size;
    const float* x  = (const float*)d_in[0];
    const float* wq = (const float*)d_in[1];
    const float* bq = (const float*)d_in[2];
    const float* wk = (const float*)d_in[3];
    const float* bk = (const float*)d_in[4];
    const float* wv = (const float*)d_in[5];
    const float* bv = (const float*)d_in[6];
    const float* wo = (const float*)d_in[7];
    const float* bo = (const float*)d_in[8];
    float* out = (float*)d_out;

    float *q, *k, *v, *attn;
    cudaGetSymbolAddress((void**)&q,    g_q);
    cudaGetSymbolAddress((void**)&k,    g_k);
    cudaGetSymbolAddress((void**)&v,    g_v);
    cudaGetSymbolAddress((void**)&attn, g_attn);

    const int ATTN_SMEM = 4 * 4352 * 4;   // 69632 B
    cudaFuncSetAttribute(attn_kernel,
                         cudaFuncAttributeMaxDynamicSharedMemorySize, ATTN_SMEM);

    dim3 ggrid(DM / 128, SQ / 128);   // (8, 32)
    gemm_bias_kernel<true><<<ggrid, 256>>>(x, wq, bq, q);
    gemm_bias_kernel<true><<<ggrid, 256>>>(x, wk, bk, k);
    gemm_bias_kernel<true><<<ggrid, 256>>>(x, wv, bv, v);

    attn_kernel<<<dim3(SQ / 64, NH), 256, ATTN_SMEM>>>(q, k, v, attn);

    gemm_bias_kernel<false><<<ggrid, 256>>>(attn, wo, bo, out);
}

// round 4
// speedup vs baseline: 3.4369x; 3.4369x over previous
#include <cuda_runtime.h>
#include <cuda_bf16.h>
#include <cuda_fp16.h>
#include <cstdint>

#define SQ 4096
#define DM 1024
#define NH 16
#define HS 64
#define QSCALE 0.125f
#define NEG -1e9f

// -------- scratch (no allocations allowed) --------
__device__ __align__(16) float g_q[NH * SQ * HS];
__device__ __align__(16) float g_k[NH * SQ * HS];
__device__ __align__(16) float g_v[NH * SQ * HS];
__device__ __align__(16) float g_attn[SQ * DM];
__device__ __align__(16) __nv_bfloat16 g_xhi[SQ * DM];
__device__ __align__(16) __nv_bfloat16 g_xlo[SQ * DM];
__device__ __align__(16) __nv_bfloat16 g_whi[4 * DM * DM];
__device__ __align__(16) __nv_bfloat16 g_wlo[4 * DM * DM];

// ============================================================================
// mma.sync / ldmatrix helpers (base sm_103 target — no 'a'-only instructions)
// ============================================================================
__device__ __forceinline__ uint32_t smem_u32(const void* p) {
    uint32_t a;
    asm("{ .reg .u64 t; cvta.to.shared.u64 t, %1; cvt.u32.u64 %0, t; }" : "=r"(a) : "l"(p));
    return a;
}

#define LDSM_X4(r0, r1, r2, r3, addr) \
    asm volatile("ldmatrix.sync.aligned.m8n8.x4.shared.b16 {%0,%1,%2,%3}, [%4];" \
                 : "=r"(r0), "=r"(r1), "=r"(r2), "=r"(r3) : "r"(addr))

#define LDSM_X4_T(r0, r1, r2, r3, addr) \
    asm volatile("ldmatrix.sync.aligned.m8n8.x4.trans.shared.b16 {%0,%1,%2,%3}, [%4];" \
                 : "=r"(r0), "=r"(r1), "=r"(r2), "=r"(r3) : "r"(addr))

__device__ __forceinline__ void mma_bf16(float4& d, const uint32_t* a, uint32_t b0, uint32_t b1) {
    asm volatile("mma.sync.aligned.m16n8k16.row.col.f32.bf16.bf16.f32 "
                 "{%0,%1,%2,%3}, {%4,%5,%6,%7}, {%8,%9}, {%0,%1,%2,%3};"
                 : "+f"(d.x), "+f"(d.y), "+f"(d.z), "+f"(d.w)
                 : "r"(a[0]), "r"(a[1]), "r"(a[2]), "r"(a[3]), "r"(b0), "r"(b1));
}

__device__ __forceinline__ void mma_f16(float4& d, const uint32_t* a, uint32_t b0, uint32_t b1) {
    asm volatile("mma.sync.aligned.m16n8k16.row.col.f32.f16.f16.f32 "
                 "{%0,%1,%2,%3}, {%4,%5,%6,%7}, {%8,%9}, {%0,%1,%2,%3};"
                 : "+f"(d.x), "+f"(d.y), "+f"(d.z), "+f"(d.w)
                 : "r"(a[0]), "r"(a[1]), "r"(a[2]), "r"(a[3]), "r"(b0), "r"(b1));
}

// ============================================================================
// fp32 -> bf16 hi/lo split helpers
// ============================================================================
__device__ __forceinline__ unsigned pack_bf2(float a, float b) {
    __nv_bfloat16 ha = __float2bfloat16_rn(a);
    __nv_bfloat16 hb = __float2bfloat16_rn(b);
    return (unsigned)__bfloat16_as_ushort(ha) | ((unsigned)__bfloat16_as_ushort(hb) << 16);
}
__device__ __forceinline__ unsigned pack_hi2(float a, float b, unsigned& lo) {
    __nv_bfloat16 ha = __float2bfloat16_rn(a);
    __nv_bfloat16 hb = __float2bfloat16_rn(b);
    float ra = a - __bfloat162float(ha);
    float rb = b - __bfloat162float(hb);
    lo = pack_bf2(ra, rb);
    return (unsigned)__bfloat16_as_ushort(ha) | ((unsigned)__bfloat16_as_ushort(hb) << 16);
}
__device__ __forceinline__ unsigned pack_h2(float a, float b) {
    __half2 h = __floats2half2_rn(a, b);
    return *(unsigned*)&h;
}
__device__ __forceinline__ unsigned pack_h2_hi(float a, float b, unsigned& lo) {
    __half ha = __float2half_rn(a);
    __half hb = __float2half_rn(b);
    float ra = a - __half2float(ha);
    float rb = b - __half2float(hb);
    lo = pack_h2(ra, rb);
    __half2 h2v = __halves2half2(ha, hb);
    return *(unsigned*)&h2v;
}

__global__ __launch_bounds__(256)
void split_kernel(const float4* __restrict__ src, uint2* __restrict__ hi,
                  uint2* __restrict__ lo, int n4)
{
    for (int i = blockIdx.x * blockDim.x + threadIdx.x; i < n4;
         i += gridDim.x * blockDim.x) {
        float4 v = src[i];
        unsigned l0, l1;
        unsigned h0 = pack_hi2(v.x, v.y, l0);
        unsigned h1 = pack_hi2(v.z, v.w, l1);
        hi[i] = make_uint2(h0, h1);
        lo[i] = make_uint2(l0, l1);
    }
}

// ============================================================================
// GEMM via mma.sync: out = A[M,K] @ W[N,K]^T + bias, bf16 hi/lo 3-term.
// 128x128 block, K-chunk 64, 256 threads = 8 warps (2 M x 4 N), warp 64x32.
// smem rows padded to 72 bf16 (144B) -> conflict-free ldmatrix.
// ============================================================================
#define GST 72          // smem row stride in bf16 elems
#define GSTB 144        // bytes

template <bool HEAD_LAYOUT>
__global__ __launch_bounds__(256, 2)
void gemm_mma(const __nv_bfloat16* __restrict__ Ahi,
              const __nv_bfloat16* __restrict__ Alo,
              int wslot,
              const float* __restrict__ b0p, const float* __restrict__ b1p,
              const float* __restrict__ b2p,
              float* __restrict__ o0, float* __restrict__ o1, float* __restrict__ o2)
{
    extern __shared__ __align__(16) char smem[];
    const int S_AHI = 0, S_ALO = 128 * GSTB, S_BHI = 2 * 128 * GSTB, S_BLO = 3 * 128 * GSTB;
    const uint32_t sb = smem_u32(smem);

    const int t = threadIdx.x;
    const int warp = t >> 5, lane = t & 31;
    const int warpM = warp >> 2, warpN = warp & 3;
    const int z = blockIdx.z;
    const int blockM = blockIdx.y * 128;
    const int blockN = blockIdx.x * 128;

    const __nv_bfloat16* Whi = g_whi + (size_t)(wslot + z) * DM * DM;
    const __nv_bfloat16* Wlo = g_wlo + (size_t)(wslot + z) * DM * DM;
    const float* bias = (z == 0) ? b0p : ((z == 1) ? b1p : b2p);
    float* out = (z == 0) ? o0 : ((z == 1) ? o1 : o2);

    float4 acc[4][4];
#pragma unroll
    for (int i = 0; i < 4; i++)
#pragma unroll
        for (int j = 0; j < 4; j++) acc[i][j] = make_float4(0.f, 0.f, 0.f, 0.f);

    for (int ch = 0; ch < 16; ch++) {
        __syncthreads();
#pragma unroll
        for (int v = 0; v < 4; v++) {
            const int idx = v * 256 + t;
            const int r = idx >> 3;
            const int c8 = (idx & 7) * 8;
            const size_t ga = (size_t)(blockM + r) * DM + ch * 64 + c8;
            const size_t gb = (size_t)(blockN + r) * DM + ch * 64 + c8;
            const uint32_t so = r * GSTB + c8 * 2;
            *(uint4*)(smem + S_AHI + so) = *(const uint4*)(Ahi + ga);
            *(uint4*)(smem + S_ALO + so) = *(const uint4*)(Alo + ga);
            *(uint4*)(smem + S_BHI + so) = *(const uint4*)(Whi + gb);
            *(uint4*)(smem + S_BLO + so) = *(const uint4*)(Wlo + gb);
        }
        __syncthreads();

#pragma unroll
        for (int ks = 0; ks < 4; ks++) {
            const uint32_t acol = (ks * 16 + (lane >> 4) * 8) * 2;
            const uint32_t bcol = (ks * 16 + ((lane >> 3) & 1) * 8) * 2;

            uint32_t a[4][4];
#pragma unroll
            for (int i = 0; i < 4; i++) {
                uint32_t ad = sb + S_AHI + (warpM * 64 + i * 16 + (lane & 15)) * GSTB + acol;
                LDSM_X4(a[i][0], a[i][1], a[i][2], a[i][3], ad);
            }
            uint32_t bh[4][2], bl[4][2];
#pragma unroll
            for (int p = 0; p < 2; p++) {
                const uint32_t brow = (warpN * 32 + p * 16 + ((lane >> 4) * 8) + (lane & 7)) * GSTB;
                uint32_t m0, m1, m2, m3;
                LDSM_X4(m0, m1, m2, m3, sb + S_BHI + brow + bcol);
                bh[2 * p][0] = m0; bh[2 * p][1] = m1; bh[2 * p + 1][0] = m2; bh[2 * p + 1][1] = m3;
                LDSM_X4(m0, m1, m2, m3, sb + S_BLO + brow + bcol);
                bl[2 * p][0] = m0; bl[2 * p][1] = m1; bl[2 * p + 1][0] = m2; bl[2 * p + 1][1] = m3;
            }
#pragma unroll
            for (int i = 0; i < 4; i++)
#pragma unroll
                for (int j = 0; j < 4; j++) {
                    mma_bf16(acc[i][j], a[i], bh[j][0], bh[j][1]);
                    mma_bf16(acc[i][j], a[i], bl[j][0], bl[j][1]);
                }
#pragma unroll
            for (int i = 0; i < 4; i++) {
                uint32_t ad = sb + S_ALO + (warpM * 64 + i * 16 + (lane & 15)) * GSTB + acol;
                LDSM_X4(a[i][0], a[i][1], a[i][2], a[i][3], ad);
            }
#pragma unroll
            for (int i = 0; i < 4; i++)
#pragma unroll
                for (int j = 0; j < 4; j++)
                    mma_bf16(acc[i][j], a[i], bh[j][0], bh[j][1]);
        }
    }

    // epilogue
#pragma unroll
    for (int i = 0; i < 4; i++) {
#pragma unroll
        for (int j = 0; j < 4; j++) {
            const int row0 = blockM + warpM * 64 + i * 16 + (lane >> 2);
            const int row1 = row0 + 8;
            const int col = blockN + warpN * 32 + j * 8 + (lane & 3) * 2;
            const float bx = bias[col], by = bias[col + 1];
            float2 r0 = make_float2(acc[i][j].x + bx, acc[i][j].y + by);
            float2 r1 = make_float2(acc[i][j].z + bx, acc[i][j].w + by);
            if (HEAD_LAYOUT) {
                const int hh = col >> 6, d = col & 63;
                *(float2*)(out + (size_t)hh * SQ * HS + (size_t)row0 * HS + d) = r0;
                *(float2*)(out + (size_t)hh * SQ * HS + (size_t)row1 * HS + d) = r1;
            } else {
                *(float2*)(out + (size_t)row0 * DM + col) = r0;
                *(float2*)(out + (size_t)row1 * DM + col) = r1;
            }
        }
    }
}

// ============================================================================
// Flash attention via mma.sync. Q,K,V fp32 [H][S][64] -> Out fp32 [S][D].
// Block: 64 q-rows x 1 head, 128 threads (4 warps, 16 q-rows each).
// S = QK^T: bf16 3-term. P fp16 x V fp16 hi/lo (2-term), V via ldmatrix.trans.
// ============================================================================
__global__ __launch_bounds__(128)
void attn_mma(const float* __restrict__ Q, const float* __restrict__ K,
              const float* __restrict__ V, float* __restrict__ Out)
{
    extern __shared__ __align__(16) char smem[];
    const int S_QHI = 0;
    const int S_QLO = 64 * GSTB;          //  9216
    const int S_KHI = 2 * 64 * GSTB;
    const int S_KLO = 3 * 64 * GSTB;
    const int S_VHI = 4 * 64 * GSTB;      // fp16
    const int S_VLO = 5 * 64 * GSTB;
    const uint32_t sb = smem_u32(smem);

    const int h  = blockIdx.y;
    const int qb = gridDim.x - 1 - blockIdx.x;
    const int t = threadIdx.x;
    const int warp = t >> 5, lane = t & 31;

    const float* Qh = Q + (size_t)h * SQ * HS;
    const float* Kh = K + (size_t)h * SQ * HS;
    const float* Vh = V + (size_t)h * SQ * HS;

    // ---- load + split Q (scaled) ----
#pragma unroll
    for (int v = 0; v < 8; v++) {
        const int idx = v * 128 + t;
        const int r = idx >> 4;
        const int c4 = (idx & 15) * 4;
        float4 qv = *(const float4*)(Qh + (size_t)(qb * 64 + r) * HS + c4);
        qv.x *= QSCALE; qv.y *= QSCALE; qv.z *= QSCALE; qv.w *= QSCALE;
        unsigned l0, l1;
        unsigned h0 = pack_hi2(qv.x, qv.y, l0);
        unsigned h1 = pack_hi2(qv.z, qv.w, l1);
        const uint32_t so = r * GSTB + c4 * 2;
        *(uint2*)(smem + S_QHI + so) = make_uint2(h0, h1);
        *(uint2*)(smem + S_QLO + so) = make_uint2(l0, l1);
    }
    __syncthreads();

    // ---- preload Q fragments (held in registers for whole kernel) ----
    uint32_t qh[4][4], ql[4][4];
#pragma unroll
    for (int ks = 0; ks < 4; ks++) {
        const uint32_t ro = (warp * 16 + (lane & 15)) * GSTB + (ks * 16 + (lane >> 4) * 8) * 2;
        LDSM_X4(qh[ks][0], qh[ks][1], qh[ks][2], qh[ks][3], sb + S_QHI + ro);
        LDSM_X4(ql[ks][0], ql[ks][1], ql[ks][2], ql[ks][3], sb + S_QLO + ro);
    }

    float4 o[8];
#pragma unroll
    for (int f = 0; f < 8; f++) o[f] = make_float4(0.f, 0.f, 0.f, 0.f);
    float m0 = -1e30f, m1 = -1e30f, l0s = 0.f, l1s = 0.f;

    for (int kt = 0; kt <= qb; kt++) {
        __syncthreads();
        // ---- load + split K (bf16) and V (fp16) tiles ----
#pragma unroll
        for (int v = 0; v < 8; v++) {
            const int idx = v * 128 + t;
            const int r = idx >> 4;
            const int c4 = (idx & 15) * 4;
            const size_t g = (size_t)(kt * 64 + r) * HS + c4;
            const uint32_t so = r * GSTB + c4 * 2;
            float4 kv = *(const float4*)(Kh + g);
            unsigned kl0, kl1;
            unsigned kh0 = pack_hi2(kv.x, kv.y, kl0);
            unsigned kh1 = pack_hi2(kv.z, kv.w, kl1);
            *(uint2*)(smem + S_KHI + so) = make_uint2(kh0, kh1);
            *(uint2*)(smem + S_KLO + so) = make_uint2(kl0, kl1);
            float4 vv = *(const float4*)(Vh + g);
            unsigned vl0, vl1;
            unsigned vh0 = pack_h2_hi(vv.x, vv.y, vl0);
            unsigned vh1 = pack_h2_hi(vv.z, vv.w, vl1);
            *(uint2*)(smem + S_VHI + so) = make_uint2(vh0, vh1);
            *(uint2*)(smem + S_VLO + so) = make_uint2(vl0, vl1);
        }
        __syncthreads();

        // ---- S = Q K^T (bf16 3-term) ----
        float4 s[8];
#pragma unroll
        for (int f = 0; f < 8; f++) s[f] = make_float4(0.f, 0.f, 0.f, 0.f);

#pragma unroll
        for (int ks = 0; ks < 4; ks++) {
            const uint32_t bcol = (ks * 16 + ((lane >> 3) & 1) * 8) * 2;
            uint32_t bh[8][2], bl[8][2];
#pragma unroll
            for (int p = 0; p < 4; p++) {
                const uint32_t brow = (p * 16 + ((lane >> 4) * 8) + (lane & 7)) * GSTB;
                uint32_t m0r, m1r, m2r, m3r;
                LDSM_X4(m0r, m1r, m2r, m3r, sb + S_KHI + brow + bcol);
                bh[2 * p][0] = m0r; bh[2 * p][1] = m1r; bh[2 * p + 1][0] = m2r; bh[2 * p + 1][1] = m3r;
                LDSM_X4(m0r, m1r, m2r, m3r, sb + S_KLO + brow + bcol);
                bl[2 * p][0] = m0r; bl[2 * p][1] = m1r; bl[2 * p + 1][0] = m2r; bl[2 * p + 1][1] = m3r;
            }
#pragma unroll
            for (int f = 0; f < 8; f++) {
                mma_bf16(s[f], qh[ks], bh[f][0], bh[f][1]);
                mma_bf16(s[f], qh[ks], bl[f][0], bl[f][1]);
                mma_bf16(s[f], ql[ks], bh[f][0], bh[f][1]);
            }
        }

        // ---- causal mask on diagonal tile ----
        if (kt == qb) {
            const int q0 = qb * 64 + warp * 16 + (lane >> 2);
            const int q1 = q0 + 8;
#pragma unroll
            for (int f = 0; f < 8; f++) {
                const int kc = kt * 64 + f * 8 + (lane & 3) * 2;
                if (kc > q0)     s[f].x = NEG;
                if (kc + 1 > q0) s[f].y = NEG;
                if (kc > q1)     s[f].z = NEG;
                if (kc + 1 > q1) s[f].w = NEG;
            }
        }

        // ---- online softmax ----
        float rmax0 = NEG, rmax1 = NEG;
#pragma unroll
        for (int f = 0; f < 8; f++) {
            rmax0 = fmaxf(rmax0, fmaxf(s[f].x, s[f].y));
            rmax1 = fmaxf(rmax1, fmaxf(s[f].z, s[f].w));
        }
        rmax0 = fmaxf(rmax0, __shfl_xor_sync(0xffffffffu, rmax0, 1));
        rmax0 = fmaxf(rmax0, __shfl_xor_sync(0xffffffffu, rmax0, 2));
        rmax1 = fmaxf(rmax1, __shfl_xor_sync(0xffffffffu, rmax1, 1));
        rmax1 = fmaxf(rmax1, __shfl_xor_sync(0xffffffffu, rmax1, 2));

        const float mn0 = fmaxf(m0, rmax0);
        const float mn1 = fmaxf(m1, rmax1);
        const float c0 = __expf(m0 - mn0);
        const float c1 = __expf(m1 - mn1);

        float rs0 = 0.f, rs1 = 0.f;
#pragma unroll
        for (int f = 0; f < 8; f++) {
            s[f].x = __expf(s[f].x - mn0);
            s[f].y = __expf(s[f].y - mn0);
            s[f].z = __expf(s[f].z - mn1);
            s[f].w = __expf(s[f].w - mn1);
            rs0 += s[f].x + s[f].y;
            rs1 += s[f].z + s[f].w;
        }
        rs0 += __shfl_xor_sync(0xffffffffu, rs0, 1);
        rs0 += __shfl_xor_sync(0xffffffffu, rs0, 2);
        rs1 += __shfl_xor_sync(0xffffffffu, rs1, 1);
        rs1 += __shfl_xor_sync(0xffffffffu, rs1, 2);

        l0s = l0s * c0 + rs0;
        l1s = l1s * c1 + rs1;
        m0 = mn0; m1 = mn1;
#pragma unroll
        for (int f = 0; f < 8; f++) {
            o[f].x *= c0; o[f].y *= c0; o[f].z *= c1; o[f].w *= c1;
        }

        // ---- O += P V  (P fp16, V fp16 hi/lo via ldmatrix.trans) ----
#pragma unroll
        for (int ks = 0; ks < 4; ks++) {
            uint32_t ap[4];
            ap[0] = pack_h2(s[2 * ks].x,     s[2 * ks].y);
            ap[1] = pack_h2(s[2 * ks].z,     s[2 * ks].w);
            ap[2] = pack_h2(s[2 * ks + 1].x, s[2 * ks + 1].y);
            ap[3] = pack_h2(s[2 * ks + 1].z, s[2 * ks + 1].w);

            uint32_t vh[8][2], vl[8][2];
#pragma unroll
            for (int g = 0; g < 4; g++) {
                const uint32_t vrow = (ks * 16 + (lane & 7) + ((lane >> 3) & 1) * 8) * GSTB;
                const uint32_t vcol = (g * 16 + (lane >> 4) * 8) * 2;
                uint32_t m0r, m1r, m2r, m3r;
                LDSM_X4_T(m0r, m1r, m2r, m3r, sb + S_VHI + vrow + vcol);
                vh[2 * g][0] = m0r; vh[2 * g][1] = m1r; vh[2 * g + 1][0] = m2r; vh[2 * g + 1][1] = m3r;
                LDSM_X4_T(m0r, m1r, m2r, m3r, sb + S_VLO + vrow + vcol);
                vl[2 * g][0] = m0r; vl[2 * g][1] = m1r; vl[2 * g + 1][0] = m2r; vl[2 * g + 1][1] = m3r;
            }
#pragma unroll
            for (int f = 0; f < 8; f++) {
                mma_f16(o[f], ap, vh[f][0], vh[f][1]);
                mma_f16(o[f], ap, vl[f][0], vl[f][1]);
            }
        }
    }

    // ---- normalize + write ----
    const float inv0 = 1.f / l0s;
    const float inv1 = 1.f / l1s;
    const int r0 = qb * 64 + warp * 16 + (lane >> 2);
    const int r1 = r0 + 8;
#pragma unroll
    for (int f = 0; f < 8; f++) {
        const int col = h * HS + f * 8 + (lane & 3) * 2;
        *(float2*)(Out + (size_t)r0 * DM + col) = make_float2(o[f].x * inv0, o[f].y * inv0);
        *(float2*)(Out + (size_t)r1 * DM + col) = make_float2(o[f].z * inv1, o[f].w * inv1);
    }
}

// ============================================================================
// launch
// ============================================================================
extern "C" void kernel_launch(void* const* d_in, const int* in_sizes, int n_in,
                              void* d_out, int out_size)
{
    (void)in_sizes; (void)n_in; (void)out_size;
    const float* x  = (const float*)d_in[0];
    const float* wq = (const float*)d_in[1];
    const float* bq = (const float*)d_in[2];
    const float* wk = (const float*)d_in[3];
    const float* bk = (const float*)d_in[4];
    const float* wv = (const float*)d_in[5];
    const float* bv = (const float*)d_in[6];
    const float* wo = (const float*)d_in[7];
    const float* bo = (const float*)d_in[8];
    float* out = (float*)d_out;

    float *q, *k, *v, *attn;
    __nv_bfloat16 *xhi, *xlo, *whi, *wlo;
    cudaGetSymbolAddress((void**)&q,    g_q);
    cudaGetSymbolAddress((void**)&k,    g_k);
    cudaGetSymbolAddress((void**)&v,    g_v);
    cudaGetSymbolAddress((void**)&attn, g_attn);
    cudaGetSymbolAddress((void**)&xhi,  g_xhi);
    cudaGetSymbolAddress((void**)&xlo,  g_xlo);
    cudaGetSymbolAddress((void**)&whi,  g_whi);
    cudaGetSymbolAddress((void**)&wlo,  g_wlo);

    const int GEMM_SMEM = 4 * 128 * GSTB;   // 73728
    const int ATTN_SMEM = 6 * 64 * GSTB;    // 55296
    cudaFuncSetAttribute(gemm_mma<true>,
                         cudaFuncAttributeMaxDynamicSharedMemorySize, GEMM_SMEM);
    cudaFuncSetAttribute(gemm_mma<false>,
                         cudaFuncAttributeMaxDynamicSharedMemorySize, GEMM_SMEM);
    cudaFuncSetAttribute(attn_mma,
                         cudaFuncAttributeMaxDynamicSharedMemorySize, ATTN_SMEM);

    const int NX4 = SQ * DM / 4;
    const int NW4 = DM * DM / 4;

    split_kernel<<<1024, 256>>>((const float4*)x, (uint2*)xhi, (uint2*)xlo, NX4);
    split_kernel<<<512, 256>>>((const float4*)wq, (uint2*)(whi + 0 * DM * DM),
                               (uint2*)(wlo + 0 * DM * DM), NW4);
    split_kernel<<<512, 256>>>((const float4*)wk, (uint2*)(whi + 1 * DM * DM),
                               (uint2*)(wlo + 1 * DM * DM), NW4);
    split_kernel<<<512, 256>>>((const float4*)wv, (uint2*)(whi + 2 * DM * DM),
                               (uint2*)(wlo + 2 * DM * DM), NW4);
    split_kernel<<<512, 256>>>((const float4*)wo, (uint2*)(whi + 3 * DM * DM),
                               (uint2*)(wlo + 3 * DM * DM), NW4);

    gemm_mma<true><<<dim3(DM / 128, SQ / 128, 3), 256, GEMM_SMEM>>>(
        xhi, xlo, 0, bq, bk, bv, q, k, v);

    attn_mma<<<dim3(SQ / 64, NH), 128, ATTN_SMEM>>>(q, k, v, attn);

    split_kernel<<<1024, 256>>>((const float4*)attn, (uint2*)xhi, (uint2*)xlo, NX4);
    gemm_mma<false><<<dim3(DM / 128, SQ / 128, 1), 256, GEMM_SMEM>>>(
        xhi, xlo, 3, bo, bo, bo, out, out, out);
}